// round 11
// baseline (speedup 1.0000x reference)
#include <cuda_runtime.h>
#include <cuda_bf16.h>

// Shapes (fixed by the problem)
#define DIMN 1024
#define HH 8
#define DD 64
#define LL 256
#define HD 512           // H*D
#define OUT_Y (LL*DIMN)  // 262144

// ---------------- scratch (device globals; no allocation allowed) ----------
__device__ float  g_part[16*LL*DIMN];    // split-K partials (16MB)
__device__ float2 g_xc[LL*HD];
__device__ float2 g_a[LL*HD];
__device__ float2 g_vinv[HH*DD*DD];
__device__ float2 g_w[(LL+1)*HD];
__device__ float2 g_heig[LL*HD];
__device__ float2 g_sP[16*HD];
__device__ float2 g_sQ[16*HD];
__device__ float2 g_sIn[16*HD];

// bf16 hi/lo pre-split operands (uint4 = 8 bf16)
__device__ uint4 g_xh [LL*DIMN/8],    g_xl [LL*DIMN/8];
__device__ uint4 g_w1h[DIMN*DIMN/8],  g_w1l[DIMN*DIMN/8];
__device__ uint4 g_w2h[DIMN*2*DIMN/8],g_w2l[DIMN*2*DIMN/8];
__device__ uint4 g_o1h[DIMN*DIMN/8],  g_o1l[DIMN*DIMN/8];
__device__ uint4 g_o2h[DIMN*DIMN/8],  g_o2l[DIMN*DIMN/8];
__device__ uint4 g_t1h[LL*DIMN/8],    g_t1l[LL*DIMN/8];
__device__ uint4 g_hrh[LL*DIMN/8],    g_hrl[LL*DIMN/8];
__device__ uint4 g_y1h[LL*DIMN/8],    g_y1l[LL*DIMN/8];

__device__ __forceinline__ float2 cmulf(float2 a, float2 b) {
    return make_float2(a.x*b.x - a.y*b.y, a.x*b.y + a.y*b.x);
}

// ---------------- bf16 split helpers ---------------------------------------
__device__ __forceinline__ unsigned pack2(float v0, float v1) {
    unsigned r;
    asm("cvt.rn.bf16x2.f32 %0, %1, %2;" : "=r"(r) : "f"(v1), "f"(v0));
    return r;
}
__device__ __forceinline__ void splitw(float v0, float v1, unsigned& h, unsigned& l) {
    h = pack2(v0, v1);
    float h0 = __uint_as_float(h << 16);
    float h1 = __uint_as_float(h & 0xFFFF0000u);
    l = pack2(v0 - h0, v1 - h1);
}
__device__ __forceinline__ void mma_bf16(float* c, const unsigned* a, const unsigned* b) {
    asm volatile(
        "mma.sync.aligned.m16n8k16.row.col.f32.bf16.bf16.f32 "
        "{%0,%1,%2,%3}, {%4,%5,%6,%7}, {%8,%9}, {%0,%1,%2,%3};\n"
        : "+f"(c[0]), "+f"(c[1]), "+f"(c[2]), "+f"(c[3])
        : "r"(a[0]), "r"(a[1]), "r"(a[2]), "r"(a[3]), "r"(b[0]), "r"(b[1]));
}
__device__ __forceinline__ void ldsm4(unsigned& r0, unsigned& r1, unsigned& r2, unsigned& r3, unsigned addr) {
    asm volatile("ldmatrix.sync.aligned.m8n8.x4.shared.b16 {%0,%1,%2,%3}, [%4];"
        : "=r"(r0), "=r"(r1), "=r"(r2), "=r"(r3) : "r"(addr));
}
__device__ __forceinline__ void ldsm4t(unsigned& r0, unsigned& r1, unsigned& r2, unsigned& r3, unsigned addr) {
    asm volatile("ldmatrix.sync.aligned.m8n8.x4.trans.shared.b16 {%0,%1,%2,%3}, [%4];"
        : "=r"(r0), "=r"(r1), "=r"(r2), "=r"(r3) : "r"(addr));
}

// ---------------- conv: f32 tensors -> bf16 hi/lo arrays -------------------
__device__ __forceinline__ void conv8(const float* __restrict__ s,
                                      uint4* __restrict__ dh, uint4* __restrict__ dl,
                                      int i)
{
    float4 v0 = ((const float4*)s)[2*i];
    float4 v1 = ((const float4*)s)[2*i+1];
    uint4 h, l;
    splitw(v0.x, v0.y, h.x, l.x); splitw(v0.z, v0.w, h.y, l.y);
    splitw(v1.x, v1.y, h.z, l.z); splitw(v1.z, v1.w, h.w, l.w);
    dh[i] = h; dl[i] = l;
}
// tasks: x 32768 | w_in1 131072 | w_in2 262144 | w_out1 131072 | w_out2 131072
__global__ void conv_kernel(const float* __restrict__ x,
                            const float* __restrict__ w1,
                            const float* __restrict__ w2,
                            const float* __restrict__ o1,
                            const float* __restrict__ o2)
{
    int id = blockIdx.x*blockDim.x + threadIdx.x;
    if      (id < 32768)  conv8(x,  g_xh,  g_xl,  id);
    else if (id < 163840) conv8(w1, g_w1h, g_w1l, id - 32768);
    else if (id < 425984) conv8(w2, g_w2h, g_w2l, id - 163840);
    else if (id < 557056) conv8(o1, g_o1h, g_o1l, id - 425984);
    else                  conv8(o2, g_o2h, g_o2l, id - 557056);
}

// ---------------- split-K bf16 GEMM: P[z] = Ah@Bh + Ah@Bl + Al@Bh ----------
// Block 64x128, BK=32, 8 warps (2M x 4N), warp 32x32, m16n8k16.
// smem element offsets (ushort): Ah 0, Al 2560, Bh 5120, Bl 9472 (tot 13824)
#define SA_PITCH 40    // A row pitch (32 + 8) elements
#define SB_PITCH 136   // B row pitch (128 + 8) elements
#define OFF_AL 2560
#define OFF_BH 5120
#define OFF_BL 9472
__global__ __launch_bounds__(256) void gemm_bf(
    const ushort* __restrict__ Ah, const ushort* __restrict__ Al,
    const ushort* __restrict__ Bh, const ushort* __restrict__ Bl,
    float* __restrict__ P, int M, int N, int K, int ksplit)
{
    __shared__ ushort sm[13824];

    const int tid  = threadIdx.x;
    const int lane = tid & 31;
    const int wid  = tid >> 5;
    const int wm   = wid & 1;
    const int wn   = wid >> 1;

    const int ksub = K / ksplit;
    const int k0g  = blockIdx.z * ksub;
    const int nc   = ksub >> 5;

    float acc[2][4][4] = {};

    // copy assignments
    const int arow = tid >> 2;             // 0..63
    const int ak8  = (tid & 3) << 3;       // 0,8,16,24
    const ushort* Aph = Ah + (size_t)(blockIdx.y*64 + arow)*K + k0g + ak8;
    const ushort* Apl = Al + (size_t)(blockIdx.y*64 + arow)*K + k0g + ak8;
    // B: two segments per matrix
    const int bi0 = tid,        bk0 = bi0 >> 4, bn0 = (bi0 & 15) << 3;
    const int bi1 = tid + 256,  bk1 = bi1 >> 4, bn1 = (bi1 & 15) << 3;
    const ushort* Bph = Bh + (size_t)k0g*N + blockIdx.x*128;
    const ushort* Bpl = Bl + (size_t)k0g*N + blockIdx.x*128;

    unsigned smem_u = (unsigned)__cvta_generic_to_shared(sm);
    // ldmatrix lane offsets
    const int aoff = ((lane & 7) + ((lane >> 3) & 1)*8)*SA_PITCH + ((lane >> 4) & 1)*8;
    const int boff = ((lane >> 4)*16 + ((lane >> 3) & 1)*8 + (lane & 7))*SB_PITCH;

    uint4 pa_h = *(const uint4*)Aph;
    uint4 pa_l = *(const uint4*)Apl;
    uint4 pb_h0 = *(const uint4*)(Bph + (size_t)bk0*N + bn0);
    uint4 pb_h1 = *(const uint4*)(Bph + (size_t)bk1*N + bn1);
    uint4 pb_l0 = *(const uint4*)(Bpl + (size_t)bk0*N + bn0);
    uint4 pb_l1 = *(const uint4*)(Bpl + (size_t)bk1*N + bn1);

    for (int c = 0; c < nc; c++) {
        if (c) __syncthreads();
        *(uint4*)&sm[arow*SA_PITCH + ak8]              = pa_h;
        *(uint4*)&sm[OFF_AL + arow*SA_PITCH + ak8]     = pa_l;
        *(uint4*)&sm[OFF_BH + bk0*SB_PITCH + bn0]      = pb_h0;
        *(uint4*)&sm[OFF_BH + bk1*SB_PITCH + bn1]      = pb_h1;
        *(uint4*)&sm[OFF_BL + bk0*SB_PITCH + bn0]      = pb_l0;
        *(uint4*)&sm[OFF_BL + bk1*SB_PITCH + bn1]      = pb_l1;
        __syncthreads();
        if (c + 1 < nc) {
            int kd = (c+1)*32;
            pa_h  = *(const uint4*)(Aph + kd);
            pa_l  = *(const uint4*)(Apl + kd);
            pb_h0 = *(const uint4*)(Bph + (size_t)(kd + bk0)*N + bn0);
            pb_h1 = *(const uint4*)(Bph + (size_t)(kd + bk1)*N + bn1);
            pb_l0 = *(const uint4*)(Bpl + (size_t)(kd + bk0)*N + bn0);
            pb_l1 = *(const uint4*)(Bpl + (size_t)(kd + bk1)*N + bn1);
        }

        // A fragments: 8 ldmatrix.x4 (hi + lo for 2ma x 2ka)
        unsigned ah[2][2][4], al_[2][2][4];
#pragma unroll
        for (int ma = 0; ma < 2; ma++)
#pragma unroll
            for (int ka = 0; ka < 2; ka++) {
                unsigned base = smem_u + 2*((wm*32 + ma*16)*SA_PITCH + ka*16 + aoff);
                ldsm4(ah[ma][ka][0], ah[ma][ka][1], ah[ma][ka][2], ah[ma][ka][3], base);
                ldsm4(al_[ma][ka][0], al_[ma][ka][1], al_[ma][ka][2], al_[ma][ka][3],
                      base + 2*OFF_AL);
            }

        // per-na: B fragments (2 ldmatrix.x4.trans) + 12 MMA
#pragma unroll
        for (int na = 0; na < 4; na++) {
            unsigned bh4[4], bl4[4];
            unsigned baseb = smem_u + 2*(OFF_BH + boff + wn*32 + na*8);
            ldsm4t(bh4[0], bh4[1], bh4[2], bh4[3], baseb);
            ldsm4t(bl4[0], bl4[1], bl4[2], bl4[3], baseb + 2*(OFF_BL - OFF_BH));
#pragma unroll
            for (int ma = 0; ma < 2; ma++)
#pragma unroll
                for (int ka = 0; ka < 2; ka++) {
                    mma_bf16(acc[ma][na], al_[ma][ka], &bh4[ka*2]);
                    mma_bf16(acc[ma][na], ah[ma][ka],  &bl4[ka*2]);
                    mma_bf16(acc[ma][na], ah[ma][ka],  &bh4[ka*2]);
                }
        }
    }

    const int g   = lane >> 2;
    const int tig = lane & 3;
    float* Pz = P + (size_t)blockIdx.z * M * N;
#pragma unroll
    for (int ma = 0; ma < 2; ma++) {
#pragma unroll
        for (int na = 0; na < 4; na++) {
            int row = blockIdx.y*64 + wm*32 + ma*16 + g;
            int col = blockIdx.x*128 + wn*32 + na*8 + 2*tig;
            *(float2*)&Pz[(size_t)row*N + col]     = make_float2(acc[ma][na][0], acc[ma][na][1]);
            *(float2*)&Pz[(size_t)(row+8)*N + col] = make_float2(acc[ma][na][2], acc[ma][na][3]);
        }
    }
}

// ---------------- reduce split-K partials + bias + silu -> bf16 hi/lo ------
__global__ void reduce_bf(const float* __restrict__ P,
                          const float* __restrict__ bias,
                          uint4* __restrict__ outh, uint4* __restrict__ outl,
                          int MN, int N, int ksplit, int act)
{
    int gid = blockIdx.x*blockDim.x + threadIdx.x;
    int e = gid * 4;
    if (e >= MN) return;
    float4 s = *(const float4*)(P + e);
    for (int z = 1; z < ksplit; z++) {
        float4 p = *(const float4*)(P + (size_t)z*MN + e);
        s.x += p.x; s.y += p.y; s.z += p.z; s.w += p.w;
    }
    int c = e % N;
    float4 b = *(const float4*)(bias + c);
    s.x += b.x; s.y += b.y; s.z += b.z; s.w += b.w;
    if (act) {
        s.x = s.x / (1.0f + expf(-s.x));
        s.y = s.y / (1.0f + expf(-s.y));
        s.z = s.z / (1.0f + expf(-s.z));
        s.w = s.w / (1.0f + expf(-s.w));
    }
    uint2 h, l;
    splitw(s.x, s.y, h.x, l.x);
    splitw(s.z, s.w, h.y, l.y);
    ((uint2*)outh)[gid] = h;
    ((uint2*)outl)[gid] = l;
}

// ---------------- reduce split-K partials + bias -> f32 (final y) ----------
__global__ void reduce_kernel(const float* __restrict__ P,
                              const float* __restrict__ bias,
                              float* __restrict__ C,
                              int MN, int N, int ksplit, int act)
{
    int e = (blockIdx.x*blockDim.x + threadIdx.x) * 4;
    if (e >= MN) return;
    float4 s = *(const float4*)(P + e);
    for (int z = 1; z < ksplit; z++) {
        float4 p = *(const float4*)(P + (size_t)z*MN + e);
        s.x += p.x; s.y += p.y; s.z += p.z; s.w += p.w;
    }
    int c = e % N;
    float4 b = *(const float4*)(bias + c);
    s.x += b.x; s.y += b.y; s.z += b.z; s.w += b.w;
    if (act) {
        s.x = s.x / (1.0f + expf(-s.x));
        s.y = s.y / (1.0f + expf(-s.y));
        s.z = s.z / (1.0f + expf(-s.z));
        s.w = s.w / (1.0f + expf(-s.w));
    }
    *(float4*)(C + e) = s;
}

// ---------------- reduce partials of GEMM2 and emit xc + normalized a ------
__global__ void reduce_prep_kernel(const float* __restrict__ P,
                                   const float* __restrict__ bias,
                                   float2* __restrict__ xc, float2* __restrict__ a,
                                   int ksplit)
{
    int e = blockIdx.x*blockDim.x + threadIdx.x;   // 0 .. LL*HD-1
    if (e >= LL*HD) return;
    const int MN = LL * 2 * DIMN;
    int off = e * 4;
    float4 s = *(const float4*)(P + off);
    for (int z = 1; z < ksplit; z++) {
        float4 p = *(const float4*)(P + (size_t)z*MN + off);
        s.x += p.x; s.y += p.y; s.z += p.z; s.w += p.w;
    }
    int c = off % (2*DIMN);
    float4 b = *(const float4*)(bias + c);
    float xr = s.x + b.x, xi = s.y + b.y, ar = s.z + b.z, ai = s.w + b.w;
    xc[e] = make_float2(xr, xi);
    float m2 = ar*ar + ai*ai;
    float f = (m2/(1.0f+m2)) * rsqrtf(m2);   // sigmoid(log m2) * rsqrt(m2)
    a[e] = make_float2(ar*f, ai*f);
}

// ---------------- complex 64x64 inverse (Gauss-Jordan, partial pivot) ------
__global__ __launch_bounds__(1024) void inv_kernel(
    const float* __restrict__ vr, const float* __restrict__ vi,
    float2* __restrict__ vinv)
{
    extern __shared__ float2 sh[];
    float2* Am = sh;          // 64*64
    float2* Im = sh + 4096;   // 64*64
    __shared__ float2 fac[64];
    __shared__ float2 pivval;
    __shared__ int piv;
    int h = blockIdx.x;
    int t = threadIdx.x;   // 1024 threads

    for (int i = t; i < 4096; i += 1024) {
        int n = i >> 6, o = i & 63;
        Am[i] = make_float2(vr[h*4096 + i], vi[h*4096 + i]);
        Im[i] = make_float2(n == o ? 1.0f : 0.0f, 0.0f);
    }
    __syncthreads();

    for (int k = 0; k < 64; k++) {
        if (t < 32) {
            float best = -1.0f; int bp = k;
            for (int r = k + t; r < 64; r += 32) {
                float2 v = Am[r*64+k];
                float m = v.x*v.x + v.y*v.y;
                if (m > best) { best = m; bp = r; }
            }
#pragma unroll
            for (int o = 16; o; o >>= 1) {
                float ob = __shfl_down_sync(0xffffffffu, best, o);
                int  obp = __shfl_down_sync(0xffffffffu, bp,   o);
                if (ob > best) { best = ob; bp = obp; }
            }
            if (t == 0) { piv = bp; pivval = Am[bp*64+k]; }
        }
        __syncthreads();
        const int p = piv;
        const float2 pv = pivval;
        const float im2 = 1.0f/(pv.x*pv.x + pv.y*pv.y);
        const float2 pinv = make_float2(pv.x*im2, -pv.y*im2);

        if (t < 128) {
            float2* Mm = (t < 64) ? Am : Im;
            int c = t & 63;
            float2 rp = Mm[p*64+c];
            float2 rk = Mm[k*64+c];
            Mm[k*64+c] = cmulf(rp, pinv);
            if (p != k) Mm[p*64+c] = rk;
        }
        __syncthreads();
        if (t < 64) fac[t] = Am[t*64+k];
        __syncthreads();

        {
            int c = t & 63;
            float2* Mm = ((t >> 6) & 1) ? Im : Am;
            int rs = t >> 7;                 // 0..7
            float2 pk = Mm[k*64+c];
#pragma unroll 8
            for (int r = rs; r < 64; r += 8) {
                if (r == k) continue;
                float2 f = fac[r];
                float2 v = Mm[r*64+c];
                v.x -= f.x*pk.x - f.y*pk.y;
                v.y -= f.x*pk.y + f.y*pk.x;
                Mm[r*64+c] = v;
            }
        }
        __syncthreads();
    }
    for (int i = t; i < 4096; i += 1024) vinv[h*4096 + i] = Im[i];
}

// ---------------- tiled matvec: w[li] = Vinv[h] @ [hidden | xc[li-1]] ------
__global__ __launch_bounds__(256) void matvec_vinv_t(
    const float2* __restrict__ vinv, const float2* __restrict__ xc,
    const float* __restrict__ hreal, const float* __restrict__ himag,
    float2* __restrict__ w)
{
    __shared__ float2 Vs[64*65];
    __shared__ float2 vecs[4][64];
    const int lc = blockIdx.x;   // 0..8
    const int h  = blockIdx.y;
    const int tid = threadIdx.x;
    for (int i = tid; i < 4096; i += 256) {
        int n = i >> 6, o = i & 63;
        Vs[n*65 + o] = vinv[h*4096 + i];
    }
    __syncthreads();
    const int g64 = tid >> 6;    // 0..3
    const int n   = tid & 63;
    for (int rep = 0; rep < 8; rep++) {
        int li = lc*32 + rep*4 + g64;
        if (li <= LL) {
            if (li == 0) vecs[g64][n] = make_float2(hreal[h*64+n], himag[h*64+n]);
            else         vecs[g64][n] = xc[(li-1)*HD + h*64 + n];
        }
        __syncthreads();
        if (li <= LL) {
            float2 acc = make_float2(0.0f, 0.0f);
#pragma unroll 8
            for (int o = 0; o < 64; o++) {
                float2 m = Vs[n*65 + o], v = vecs[g64][o];
                acc.x += m.x*v.x - m.y*v.y;
                acc.y += m.x*v.y + m.y*v.x;
            }
            w[li*HD + h*64 + n] = acc;
        }
        __syncthreads();
    }
}

// ---------------- chunked scan: s[m] = a[m]*(s[m-1]+w[m]) ------------------
__global__ void scanA_kernel(const float2* __restrict__ a,
                             const float2* __restrict__ w,
                             float2* __restrict__ sP, float2* __restrict__ sQ)
{
    int c = blockIdx.x;      // 0..15
    int hd = threadIdx.x;    // 0..511
    float2 Pp = make_float2(1.0f, 0.0f);
    float2 S  = make_float2(0.0f, 0.0f);
#pragma unroll
    for (int i = 0; i < 16; i++) {
        int m = c*16 + i;
        float2 wm = w[m*HD + hd];
        float2 am = a[m*HD + hd];
        float2 t = make_float2(S.x + wm.x, S.y + wm.y);
        S  = cmulf(am, t);
        Pp = cmulf(am, Pp);
    }
    sP[c*HD + hd] = Pp;
    sQ[c*HD + hd] = S;
}
__global__ void scanB_kernel(const float2* __restrict__ sP,
                             const float2* __restrict__ sQ,
                             float2* __restrict__ sIn)
{
    int hd = threadIdx.x;
    float2 s = make_float2(0.0f, 0.0f);
#pragma unroll
    for (int c = 0; c < 16; c++) {
        sIn[c*HD + hd] = s;
        float2 p = sP[c*HD + hd];
        float2 q = sQ[c*HD + hd];
        float2 t = cmulf(p, s);
        s = make_float2(t.x + q.x, t.y + q.y);
    }
}
__global__ void scanC_kernel(const float2* __restrict__ a,
                             const float2* __restrict__ w,
                             const float2* __restrict__ sIn,
                             float2* __restrict__ heig)
{
    int c = blockIdx.x;
    int hd = threadIdx.x;
    float2 s = sIn[c*HD + hd];
#pragma unroll
    for (int i = 0; i < 16; i++) {
        int m = c*16 + i;
        float2 wm = w[m*HD + hd];
        float2 am = a[m*HD + hd];
        float2 t = make_float2(s.x + wm.x, s.y + wm.y);
        s = cmulf(am, t);
        float2 wn = w[(m+1)*HD + hd];
        heig[m*HD + hd] = make_float2(s.x + wn.x, s.y + wn.y);
    }
}

// ---------------- tiled matvec: out_h[l] = V[h] @ heig[l]; emit bf16 hr ----
__global__ __launch_bounds__(256) void matvec_v_t(
    const float* __restrict__ vr, const float* __restrict__ vi,
    const float2* __restrict__ heig,
    unsigned* __restrict__ hrh, unsigned* __restrict__ hrl,
    float* __restrict__ out, int out_size)
{
    __shared__ float2 Vs[64*65];
    __shared__ float2 vecs[4][64];
    const int lc = blockIdx.x;   // 0..7
    const int h  = blockIdx.y;
    const int tid = threadIdx.x;
    for (int i = tid; i < 4096; i += 256) {
        int n = i >> 6, o = i & 63;
        Vs[n*65 + o] = make_float2(vr[h*4096 + i], vi[h*4096 + i]);
    }
    __syncthreads();
    const int g64 = tid >> 6;
    const int n   = tid & 63;
    for (int rep = 0; rep < 8; rep++) {
        int l = lc*32 + rep*4 + g64;
        vecs[g64][n] = heig[l*HD + h*64 + n];
        __syncthreads();
        float2 acc = make_float2(0.0f, 0.0f);
#pragma unroll 8
        for (int o = 0; o < 64; o++) {
            float2 m = Vs[n*65 + o], v = vecs[g64][o];
            acc.x += m.x*v.x - m.y*v.y;
            acc.y += m.x*v.y + m.y*v.x;
        }
        // hr element pair (h*128+2n, +1) -> bf16x2 word h*64+n
        unsigned hw, lw;
        splitw(acc.x, acc.y, hw, lw);
        hrh[(size_t)l*HD + h*64 + n] = hw;
        hrl[(size_t)l*HD + h*64 + n] = lw;
        if (l == LL-1) {
            if (out_size >= OUT_Y + 2*HD) {
                out[OUT_Y + (h*64+n)*2]     = acc.x;
                out[OUT_Y + (h*64+n)*2 + 1] = acc.y;
            } else if (out_size >= OUT_Y + HD) {
                out[OUT_Y + h*64 + n] = acc.x;
            }
        }
        __syncthreads();
    }
}

// ---------------- launch ---------------------------------------------------
extern "C" void kernel_launch(void* const* d_in, const int* in_sizes, int n_in,
                              void* d_out, int out_size)
{
    const float* x        = (const float*)d_in[0];
    const float* hreal    = (const float*)d_in[1];
    const float* himag    = (const float*)d_in[2];
    const float* w_in1    = (const float*)d_in[3];
    const float* b_in1    = (const float*)d_in[4];
    const float* w_in2    = (const float*)d_in[5];
    const float* b_in2    = (const float*)d_in[6];
    const float* w_out1   = (const float*)d_in[7];
    const float* b_out1   = (const float*)d_in[8];
    const float* w_out2   = (const float*)d_in[9];
    const float* b_out2   = (const float*)d_in[10];
    const float* mvr      = (const float*)d_in[11];
    const float* mvi      = (const float*)d_in[12];
    float* out = (float*)d_out;

    float *part;
    float2 *xc, *a, *vinv, *w, *heig, *sP, *sQ, *sIn;
    cudaGetSymbolAddress((void**)&part, g_part);
    cudaGetSymbolAddress((void**)&xc,   g_xc);
    cudaGetSymbolAddress((void**)&a,    g_a);
    cudaGetSymbolAddress((void**)&vinv, g_vinv);
    cudaGetSymbolAddress((void**)&w,    g_w);
    cudaGetSymbolAddress((void**)&heig, g_heig);
    cudaGetSymbolAddress((void**)&sP,   g_sP);
    cudaGetSymbolAddress((void**)&sQ,   g_sQ);
    cudaGetSymbolAddress((void**)&sIn,  g_sIn);

    uint4 *xh,*xl,*w1h,*w1l,*w2h,*w2l,*o1h,*o1l,*o2h,*o2l,*t1h,*t1l,*hrh,*hrl,*y1h,*y1l;
    cudaGetSymbolAddress((void**)&xh,  g_xh);  cudaGetSymbolAddress((void**)&xl,  g_xl);
    cudaGetSymbolAddress((void**)&w1h, g_w1h); cudaGetSymbolAddress((void**)&w1l, g_w1l);
    cudaGetSymbolAddress((void**)&w2h, g_w2h); cudaGetSymbolAddress((void**)&w2l, g_w2l);
    cudaGetSymbolAddress((void**)&o1h, g_o1h); cudaGetSymbolAddress((void**)&o1l, g_o1l);
    cudaGetSymbolAddress((void**)&o2h, g_o2h); cudaGetSymbolAddress((void**)&o2l, g_o2l);
    cudaGetSymbolAddress((void**)&t1h, g_t1h); cudaGetSymbolAddress((void**)&t1l, g_t1l);
    cudaGetSymbolAddress((void**)&hrh, g_hrh); cudaGetSymbolAddress((void**)&hrl, g_hrl);
    cudaGetSymbolAddress((void**)&y1h, g_y1h); cudaGetSymbolAddress((void**)&y1l, g_y1l);

    cudaFuncSetAttribute(inv_kernel, cudaFuncAttributeMaxDynamicSharedMemorySize, 65536);

    const int MN1 = LL * DIMN;       // 262144

    // Vinv + operand pre-split (independent of each other)
    inv_kernel<<<HH, 1024, 65536>>>(mvr, mvi, vinv);
    conv_kernel<<<2688, 256>>>(x, w_in1, w_in2, w_out1, w_out2);

    // t1 = silu(x @ w_in1 + b_in1) -> bf16 hi/lo    split-K=16
    gemm_bf<<<dim3(DIMN/128, LL/64, 16), 256>>>(
        (const ushort*)xh, (const ushort*)xl, (const ushort*)w1h, (const ushort*)w1l,
        part, LL, DIMN, DIMN, 16);
    reduce_bf<<<(MN1/4 + 255)/256, 256>>>(part, b_in1, t1h, t1l, MN1, DIMN, 16, 1);

    // t2 partials = t1 @ w_in2 ; fused reduce -> xc, a   split-K=8
    gemm_bf<<<dim3(2*DIMN/128, LL/64, 8), 256>>>(
        (const ushort*)t1h, (const ushort*)t1l, (const ushort*)w2h, (const ushort*)w2l,
        part, LL, 2*DIMN, DIMN, 8);
    reduce_prep_kernel<<<(LL*HD + 255)/256, 256>>>(part, b_in2, xc, a, 8);

    // w[0..256] = Vinv @ [hidden, xc[0..255]]
    matvec_vinv_t<<<dim3(9, HH), 256>>>(vinv, xc, hreal, himag, w);

    // chunked diagonal recurrence
    scanA_kernel<<<16, HD>>>(a, w, sP, sQ);
    scanB_kernel<<<1, HD>>>(sP, sQ, sIn);
    scanC_kernel<<<16, HD>>>(a, w, sIn, heig);

    // back to original basis; emit bf16 hr + hidden_next
    matvec_v_t<<<dim3(8, HH), 256>>>(mvr, mvi, heig,
                                     (unsigned*)hrh, (unsigned*)hrl, out, out_size);

    // y1 = silu(hr @ w_out1 + b_out1) -> bf16 hi/lo   split-K=16
    gemm_bf<<<dim3(DIMN/128, LL/64, 16), 256>>>(
        (const ushort*)hrh, (const ushort*)hrl, (const ushort*)o1h, (const ushort*)o1l,
        part, LL, DIMN, DIMN, 16);
    reduce_bf<<<(MN1/4 + 255)/256, 256>>>(part, b_out1, y1h, y1l, MN1, DIMN, 16, 1);

    // y = y1 @ w_out2 + b_out2 -> d_out (f32)   split-K=16
    gemm_bf<<<dim3(DIMN/128, LL/64, 16), 256>>>(
        (const ushort*)y1h, (const ushort*)y1l, (const ushort*)o2h, (const ushort*)o2l,
        part, LL, DIMN, DIMN, 16);
    reduce_kernel<<<(MN1/4 + 255)/256, 256>>>(part, b_out2, out, MN1, DIMN, 16, 0);
}

// round 12
// speedup vs baseline: 1.0314x; 1.0314x over previous
#include <cuda_runtime.h>
#include <cuda_bf16.h>

// Shapes (fixed by the problem)
#define DIMN 1024
#define HH 8
#define DD 64
#define LL 256
#define HD 512           // H*D
#define OUT_Y (LL*DIMN)  // 262144

// ---------------- scratch (device globals; no allocation allowed) ----------
__device__ float  g_part[4*LL*DIMN];     // split-K partials (4MB max)
__device__ float2 g_xc[LL*HD];
__device__ float2 g_a[LL*HD];
__device__ float2 g_vinv[HH*DD*DD];
__device__ float2 g_w[(LL+1)*HD];
__device__ float2 g_heig[LL*HD];
__device__ float2 g_sP[16*HD];
__device__ float2 g_sQ[16*HD];
__device__ float2 g_sIn[16*HD];

// bf16 hi/lo pre-split operands (uint4 = 8 bf16)
__device__ uint4 g_xh [LL*DIMN/8],    g_xl [LL*DIMN/8];
__device__ uint4 g_w1h[DIMN*DIMN/8],  g_w1l[DIMN*DIMN/8];
__device__ uint4 g_w2h[DIMN*2*DIMN/8],g_w2l[DIMN*2*DIMN/8];
__device__ uint4 g_o1h[DIMN*DIMN/8],  g_o1l[DIMN*DIMN/8];
__device__ uint4 g_o2h[DIMN*DIMN/8],  g_o2l[DIMN*DIMN/8];
__device__ uint4 g_t1h[LL*DIMN/8],    g_t1l[LL*DIMN/8];
__device__ uint4 g_hrh[LL*DIMN/8],    g_hrl[LL*DIMN/8];
__device__ uint4 g_y1h[LL*DIMN/8],    g_y1l[LL*DIMN/8];

__device__ __forceinline__ float2 cmulf(float2 a, float2 b) {
    return make_float2(a.x*b.x - a.y*b.y, a.x*b.y + a.y*b.x);
}

// ---------------- bf16 split helpers ---------------------------------------
__device__ __forceinline__ unsigned pack2(float v0, float v1) {
    unsigned r;
    asm("cvt.rn.bf16x2.f32 %0, %1, %2;" : "=r"(r) : "f"(v1), "f"(v0));
    return r;
}
__device__ __forceinline__ void splitw(float v0, float v1, unsigned& h, unsigned& l) {
    h = pack2(v0, v1);
    float h0 = __uint_as_float(h << 16);
    float h1 = __uint_as_float(h & 0xFFFF0000u);
    l = pack2(v0 - h0, v1 - h1);
}
__device__ __forceinline__ void mma_bf16(float* c, const unsigned* a, const unsigned* b) {
    asm volatile(
        "mma.sync.aligned.m16n8k16.row.col.f32.bf16.bf16.f32 "
        "{%0,%1,%2,%3}, {%4,%5,%6,%7}, {%8,%9}, {%0,%1,%2,%3};\n"
        : "+f"(c[0]), "+f"(c[1]), "+f"(c[2]), "+f"(c[3])
        : "r"(a[0]), "r"(a[1]), "r"(a[2]), "r"(a[3]), "r"(b[0]), "r"(b[1]));
}
__device__ __forceinline__ void ldsm4(unsigned& r0, unsigned& r1, unsigned& r2, unsigned& r3, unsigned addr) {
    asm volatile("ldmatrix.sync.aligned.m8n8.x4.shared.b16 {%0,%1,%2,%3}, [%4];"
        : "=r"(r0), "=r"(r1), "=r"(r2), "=r"(r3) : "r"(addr));
}
__device__ __forceinline__ void ldsm4t(unsigned& r0, unsigned& r1, unsigned& r2, unsigned& r3, unsigned addr) {
    asm volatile("ldmatrix.sync.aligned.m8n8.x4.trans.shared.b16 {%0,%1,%2,%3}, [%4];"
        : "=r"(r0), "=r"(r1), "=r"(r2), "=r"(r3) : "r"(addr));
}

// ---------------- conv: f32 tensors -> bf16 hi/lo arrays -------------------
__device__ __forceinline__ void conv8(const float* __restrict__ s,
                                      uint4* __restrict__ dh, uint4* __restrict__ dl,
                                      int i)
{
    float4 v0 = ((const float4*)s)[2*i];
    float4 v1 = ((const float4*)s)[2*i+1];
    uint4 h, l;
    splitw(v0.x, v0.y, h.x, l.x); splitw(v0.z, v0.w, h.y, l.y);
    splitw(v1.x, v1.y, h.z, l.z); splitw(v1.z, v1.w, h.w, l.w);
    dh[i] = h; dl[i] = l;
}
// tasks: x 32768 | w_in1 131072 | w_in2 262144 | w_out1 131072 | w_out2 131072
__global__ void conv_kernel(const float* __restrict__ x,
                            const float* __restrict__ w1,
                            const float* __restrict__ w2,
                            const float* __restrict__ o1,
                            const float* __restrict__ o2)
{
    int id = blockIdx.x*blockDim.x + threadIdx.x;
    if      (id < 32768)  conv8(x,  g_xh,  g_xl,  id);
    else if (id < 163840) conv8(w1, g_w1h, g_w1l, id - 32768);
    else if (id < 425984) conv8(w2, g_w2h, g_w2l, id - 163840);
    else if (id < 557056) conv8(o1, g_o1h, g_o1l, id - 425984);
    else                  conv8(o2, g_o2h, g_o2l, id - 557056);
}

// ---------------- split-K bf16 GEMM: P[z] = Ah@Bh + Ah@Bl + Al@Bh ----------
// Block 64x128, BK=32, 8 warps (2M x 4N), warp 32x32, m16n8k16.
// smem element offsets (ushort): Ah 0, Al 2560, Bh 5120, Bl 9472 (tot 13824)
#define SA_PITCH 40    // A row pitch (32 + 8) elements
#define SB_PITCH 136   // B row pitch (128 + 8) elements
#define OFF_AL 2560
#define OFF_BH 5120
#define OFF_BL 9472
__global__ __launch_bounds__(256) void gemm_bf(
    const ushort* __restrict__ Ah, const ushort* __restrict__ Al,
    const ushort* __restrict__ Bh, const ushort* __restrict__ Bl,
    float* __restrict__ P, int M, int N, int K, int ksplit)
{
    __shared__ ushort sm[13824];

    const int tid  = threadIdx.x;
    const int lane = tid & 31;
    const int wid  = tid >> 5;
    const int wm   = wid & 1;
    const int wn   = wid >> 1;

    const int ksub = K / ksplit;
    const int k0g  = blockIdx.z * ksub;
    const int nc   = ksub >> 5;

    float acc[2][4][4] = {};

    // copy assignments
    const int arow = tid >> 2;             // 0..63
    const int ak8  = (tid & 3) << 3;       // 0,8,16,24
    const ushort* Aph = Ah + (size_t)(blockIdx.y*64 + arow)*K + k0g + ak8;
    const ushort* Apl = Al + (size_t)(blockIdx.y*64 + arow)*K + k0g + ak8;
    // B: two segments per matrix
    const int bi0 = tid,        bk0 = bi0 >> 4, bn0 = (bi0 & 15) << 3;
    const int bi1 = tid + 256,  bk1 = bi1 >> 4, bn1 = (bi1 & 15) << 3;
    const ushort* Bph = Bh + (size_t)k0g*N + blockIdx.x*128;
    const ushort* Bpl = Bl + (size_t)k0g*N + blockIdx.x*128;

    unsigned smem_u = (unsigned)__cvta_generic_to_shared(sm);
    // ldmatrix lane offsets
    const int aoff = ((lane & 7) + ((lane >> 3) & 1)*8)*SA_PITCH + ((lane >> 4) & 1)*8;
    const int boff = ((lane >> 4)*16 + ((lane >> 3) & 1)*8 + (lane & 7))*SB_PITCH;

    uint4 pa_h = *(const uint4*)Aph;
    uint4 pa_l = *(const uint4*)Apl;
    uint4 pb_h0 = *(const uint4*)(Bph + (size_t)bk0*N + bn0);
    uint4 pb_h1 = *(const uint4*)(Bph + (size_t)bk1*N + bn1);
    uint4 pb_l0 = *(const uint4*)(Bpl + (size_t)bk0*N + bn0);
    uint4 pb_l1 = *(const uint4*)(Bpl + (size_t)bk1*N + bn1);

    for (int c = 0; c < nc; c++) {
        if (c) __syncthreads();
        *(uint4*)&sm[arow*SA_PITCH + ak8]              = pa_h;
        *(uint4*)&sm[OFF_AL + arow*SA_PITCH + ak8]     = pa_l;
        *(uint4*)&sm[OFF_BH + bk0*SB_PITCH + bn0]      = pb_h0;
        *(uint4*)&sm[OFF_BH + bk1*SB_PITCH + bn1]      = pb_h1;
        *(uint4*)&sm[OFF_BL + bk0*SB_PITCH + bn0]      = pb_l0;
        *(uint4*)&sm[OFF_BL + bk1*SB_PITCH + bn1]      = pb_l1;
        __syncthreads();
        if (c + 1 < nc) {
            int kd = (c+1)*32;
            pa_h  = *(const uint4*)(Aph + kd);
            pa_l  = *(const uint4*)(Apl + kd);
            pb_h0 = *(const uint4*)(Bph + (size_t)(kd + bk0)*N + bn0);
            pb_h1 = *(const uint4*)(Bph + (size_t)(kd + bk1)*N + bn1);
            pb_l0 = *(const uint4*)(Bpl + (size_t)(kd + bk0)*N + bn0);
            pb_l1 = *(const uint4*)(Bpl + (size_t)(kd + bk1)*N + bn1);
        }

        // A fragments: 8 ldmatrix.x4 (hi + lo for 2ma x 2ka)
        unsigned ah[2][2][4], al_[2][2][4];
#pragma unroll
        for (int ma = 0; ma < 2; ma++)
#pragma unroll
            for (int ka = 0; ka < 2; ka++) {
                unsigned base = smem_u + 2*((wm*32 + ma*16)*SA_PITCH + ka*16 + aoff);
                ldsm4(ah[ma][ka][0], ah[ma][ka][1], ah[ma][ka][2], ah[ma][ka][3], base);
                ldsm4(al_[ma][ka][0], al_[ma][ka][1], al_[ma][ka][2], al_[ma][ka][3],
                      base + 2*OFF_AL);
            }

        // per-na: B fragments (2 ldmatrix.x4.trans) + 12 MMA
#pragma unroll
        for (int na = 0; na < 4; na++) {
            unsigned bh4[4], bl4[4];
            unsigned baseb = smem_u + 2*(OFF_BH + boff + wn*32 + na*8);
            ldsm4t(bh4[0], bh4[1], bh4[2], bh4[3], baseb);
            ldsm4t(bl4[0], bl4[1], bl4[2], bl4[3], baseb + 2*(OFF_BL - OFF_BH));
#pragma unroll
            for (int ma = 0; ma < 2; ma++)
#pragma unroll
                for (int ka = 0; ka < 2; ka++) {
                    mma_bf16(acc[ma][na], al_[ma][ka], &bh4[ka*2]);
                    mma_bf16(acc[ma][na], ah[ma][ka],  &bl4[ka*2]);
                    mma_bf16(acc[ma][na], ah[ma][ka],  &bh4[ka*2]);
                }
        }
    }

    const int g   = lane >> 2;
    const int tig = lane & 3;
    float* Pz = P + (size_t)blockIdx.z * M * N;
#pragma unroll
    for (int ma = 0; ma < 2; ma++) {
#pragma unroll
        for (int na = 0; na < 4; na++) {
            int row = blockIdx.y*64 + wm*32 + ma*16 + g;
            int col = blockIdx.x*128 + wn*32 + na*8 + 2*tig;
            *(float2*)&Pz[(size_t)row*N + col]     = make_float2(acc[ma][na][0], acc[ma][na][1]);
            *(float2*)&Pz[(size_t)(row+8)*N + col] = make_float2(acc[ma][na][2], acc[ma][na][3]);
        }
    }
}

// ---------------- reduce split-K partials + bias + silu -> bf16 hi/lo ------
__global__ void reduce_bf(const float* __restrict__ P,
                          const float* __restrict__ bias,
                          uint4* __restrict__ outh, uint4* __restrict__ outl,
                          int MN, int N, int ksplit, int act)
{
    int gid = blockIdx.x*blockDim.x + threadIdx.x;
    int e = gid * 4;
    if (e >= MN) return;
    float4 s = *(const float4*)(P + e);
    for (int z = 1; z < ksplit; z++) {
        float4 p = *(const float4*)(P + (size_t)z*MN + e);
        s.x += p.x; s.y += p.y; s.z += p.z; s.w += p.w;
    }
    int c = e % N;
    float4 b = *(const float4*)(bias + c);
    s.x += b.x; s.y += b.y; s.z += b.z; s.w += b.w;
    if (act) {
        s.x = s.x / (1.0f + expf(-s.x));
        s.y = s.y / (1.0f + expf(-s.y));
        s.z = s.z / (1.0f + expf(-s.z));
        s.w = s.w / (1.0f + expf(-s.w));
    }
    uint2 h, l;
    splitw(s.x, s.y, h.x, l.x);
    splitw(s.z, s.w, h.y, l.y);
    ((uint2*)outh)[gid] = h;
    ((uint2*)outl)[gid] = l;
}

// ---------------- reduce split-K partials + bias -> f32 (final y) ----------
__global__ void reduce_kernel(const float* __restrict__ P,
                              const float* __restrict__ bias,
                              float* __restrict__ C,
                              int MN, int N, int ksplit, int act)
{
    int e = (blockIdx.x*blockDim.x + threadIdx.x) * 4;
    if (e >= MN) return;
    float4 s = *(const float4*)(P + e);
    for (int z = 1; z < ksplit; z++) {
        float4 p = *(const float4*)(P + (size_t)z*MN + e);
        s.x += p.x; s.y += p.y; s.z += p.z; s.w += p.w;
    }
    int c = e % N;
    float4 b = *(const float4*)(bias + c);
    s.x += b.x; s.y += b.y; s.z += b.z; s.w += b.w;
    if (act) {
        s.x = s.x / (1.0f + expf(-s.x));
        s.y = s.y / (1.0f + expf(-s.y));
        s.z = s.z / (1.0f + expf(-s.z));
        s.w = s.w / (1.0f + expf(-s.w));
    }
    *(float4*)(C + e) = s;
}

// ---------------- reduce partials of GEMM2 and emit xc + normalized a ------
__global__ void reduce_prep_kernel(const float* __restrict__ P,
                                   const float* __restrict__ bias,
                                   float2* __restrict__ xc, float2* __restrict__ a,
                                   int ksplit)
{
    int e = blockIdx.x*blockDim.x + threadIdx.x;   // 0 .. LL*HD-1
    if (e >= LL*HD) return;
    const int MN = LL * 2 * DIMN;
    int off = e * 4;
    float4 s = *(const float4*)(P + off);
    for (int z = 1; z < ksplit; z++) {
        float4 p = *(const float4*)(P + (size_t)z*MN + off);
        s.x += p.x; s.y += p.y; s.z += p.z; s.w += p.w;
    }
    int c = off % (2*DIMN);
    float4 b = *(const float4*)(bias + c);
    float xr = s.x + b.x, xi = s.y + b.y, ar = s.z + b.z, ai = s.w + b.w;
    xc[e] = make_float2(xr, xi);
    float m2 = ar*ar + ai*ai;
    float f = (m2/(1.0f+m2)) * rsqrtf(m2);   // sigmoid(log m2) * rsqrt(m2)
    a[e] = make_float2(ar*f, ai*f);
}

// ---------------- complex 64x64 inverse (Gauss-Jordan, partial pivot) ------
__global__ __launch_bounds__(1024) void inv_kernel(
    const float* __restrict__ vr, const float* __restrict__ vi,
    float2* __restrict__ vinv)
{
    extern __shared__ float2 sh[];
    float2* Am = sh;          // 64*64
    float2* Im = sh + 4096;   // 64*64
    __shared__ float2 fac[64];
    __shared__ float2 pivval;
    __shared__ int piv;
    int h = blockIdx.x;
    int t = threadIdx.x;   // 1024 threads

    for (int i = t; i < 4096; i += 1024) {
        int n = i >> 6, o = i & 63;
        Am[i] = make_float2(vr[h*4096 + i], vi[h*4096 + i]);
        Im[i] = make_float2(n == o ? 1.0f : 0.0f, 0.0f);
    }
    __syncthreads();

    for (int k = 0; k < 64; k++) {
        if (t < 32) {
            float best = -1.0f; int bp = k;
            for (int r = k + t; r < 64; r += 32) {
                float2 v = Am[r*64+k];
                float m = v.x*v.x + v.y*v.y;
                if (m > best) { best = m; bp = r; }
            }
#pragma unroll
            for (int o = 16; o; o >>= 1) {
                float ob = __shfl_down_sync(0xffffffffu, best, o);
                int  obp = __shfl_down_sync(0xffffffffu, bp,   o);
                if (ob > best) { best = ob; bp = obp; }
            }
            if (t == 0) { piv = bp; pivval = Am[bp*64+k]; }
        }
        __syncthreads();
        const int p = piv;
        const float2 pv = pivval;
        const float im2 = 1.0f/(pv.x*pv.x + pv.y*pv.y);
        const float2 pinv = make_float2(pv.x*im2, -pv.y*im2);

        if (t < 128) {
            float2* Mm = (t < 64) ? Am : Im;
            int c = t & 63;
            float2 rp = Mm[p*64+c];
            float2 rk = Mm[k*64+c];
            Mm[k*64+c] = cmulf(rp, pinv);
            if (p != k) Mm[p*64+c] = rk;
        }
        __syncthreads();
        if (t < 64) fac[t] = Am[t*64+k];
        __syncthreads();

        {
            int c = t & 63;
            float2* Mm = ((t >> 6) & 1) ? Im : Am;
            int rs = t >> 7;                 // 0..7
            float2 pk = Mm[k*64+c];
#pragma unroll 8
            for (int r = rs; r < 64; r += 8) {
                if (r == k) continue;
                float2 f = fac[r];
                float2 v = Mm[r*64+c];
                v.x -= f.x*pk.x - f.y*pk.y;
                v.y -= f.x*pk.y + f.y*pk.x;
                Mm[r*64+c] = v;
            }
        }
        __syncthreads();
    }
    for (int i = t; i < 4096; i += 1024) vinv[h*4096 + i] = Im[i];
}

// ---------------- tiled matvec: w[li] = Vinv[h] @ [hidden | xc[li-1]] ------
__global__ __launch_bounds__(256) void matvec_vinv_t(
    const float2* __restrict__ vinv, const float2* __restrict__ xc,
    const float* __restrict__ hreal, const float* __restrict__ himag,
    float2* __restrict__ w)
{
    __shared__ float2 Vs[64*65];
    __shared__ float2 vecs[4][64];
    const int lc = blockIdx.x;   // 0..8
    const int h  = blockIdx.y;
    const int tid = threadIdx.x;
    for (int i = tid; i < 4096; i += 256) {
        int n = i >> 6, o = i & 63;
        Vs[n*65 + o] = vinv[h*4096 + i];
    }
    __syncthreads();
    const int g64 = tid >> 6;    // 0..3
    const int n   = tid & 63;
    for (int rep = 0; rep < 8; rep++) {
        int li = lc*32 + rep*4 + g64;
        if (li <= LL) {
            if (li == 0) vecs[g64][n] = make_float2(hreal[h*64+n], himag[h*64+n]);
            else         vecs[g64][n] = xc[(li-1)*HD + h*64 + n];
        }
        __syncthreads();
        if (li <= LL) {
            float2 acc = make_float2(0.0f, 0.0f);
#pragma unroll 8
            for (int o = 0; o < 64; o++) {
                float2 m = Vs[n*65 + o], v = vecs[g64][o];
                acc.x += m.x*v.x - m.y*v.y;
                acc.y += m.x*v.y + m.y*v.x;
            }
            w[li*HD + h*64 + n] = acc;
        }
        __syncthreads();
    }
}

// ---------------- chunked scan: s[m] = a[m]*(s[m-1]+w[m]) ------------------
__global__ void scanA_kernel(const float2* __restrict__ a,
                             const float2* __restrict__ w,
                             float2* __restrict__ sP, float2* __restrict__ sQ)
{
    int c = blockIdx.x;      // 0..15
    int hd = threadIdx.x;    // 0..511
    float2 Pp = make_float2(1.0f, 0.0f);
    float2 S  = make_float2(0.0f, 0.0f);
#pragma unroll
    for (int i = 0; i < 16; i++) {
        int m = c*16 + i;
        float2 wm = w[m*HD + hd];
        float2 am = a[m*HD + hd];
        float2 t = make_float2(S.x + wm.x, S.y + wm.y);
        S  = cmulf(am, t);
        Pp = cmulf(am, Pp);
    }
    sP[c*HD + hd] = Pp;
    sQ[c*HD + hd] = S;
}
__global__ void scanB_kernel(const float2* __restrict__ sP,
                             const float2* __restrict__ sQ,
                             float2* __restrict__ sIn)
{
    int hd = threadIdx.x;
    float2 s = make_float2(0.0f, 0.0f);
#pragma unroll
    for (int c = 0; c < 16; c++) {
        sIn[c*HD + hd] = s;
        float2 p = sP[c*HD + hd];
        float2 q = sQ[c*HD + hd];
        float2 t = cmulf(p, s);
        s = make_float2(t.x + q.x, t.y + q.y);
    }
}
__global__ void scanC_kernel(const float2* __restrict__ a,
                             const float2* __restrict__ w,
                             const float2* __restrict__ sIn,
                             float2* __restrict__ heig)
{
    int c = blockIdx.x;
    int hd = threadIdx.x;
    float2 s = sIn[c*HD + hd];
#pragma unroll
    for (int i = 0; i < 16; i++) {
        int m = c*16 + i;
        float2 wm = w[m*HD + hd];
        float2 am = a[m*HD + hd];
        float2 t = make_float2(s.x + wm.x, s.y + wm.y);
        s = cmulf(am, t);
        float2 wn = w[(m+1)*HD + hd];
        heig[m*HD + hd] = make_float2(s.x + wn.x, s.y + wn.y);
    }
}

// ---------------- tiled matvec: out_h[l] = V[h] @ heig[l]; emit bf16 hr ----
__global__ __launch_bounds__(256) void matvec_v_t(
    const float* __restrict__ vr, const float* __restrict__ vi,
    const float2* __restrict__ heig,
    unsigned* __restrict__ hrh, unsigned* __restrict__ hrl,
    float* __restrict__ out, int out_size)
{
    __shared__ float2 Vs[64*65];
    __shared__ float2 vecs[4][64];
    const int lc = blockIdx.x;   // 0..7
    const int h  = blockIdx.y;
    const int tid = threadIdx.x;
    for (int i = tid; i < 4096; i += 256) {
        int n = i >> 6, o = i & 63;
        Vs[n*65 + o] = make_float2(vr[h*4096 + i], vi[h*4096 + i]);
    }
    __syncthreads();
    const int g64 = tid >> 6;
    const int n   = tid & 63;
    for (int rep = 0; rep < 8; rep++) {
        int l = lc*32 + rep*4 + g64;
        vecs[g64][n] = heig[l*HD + h*64 + n];
        __syncthreads();
        float2 acc = make_float2(0.0f, 0.0f);
#pragma unroll 8
        for (int o = 0; o < 64; o++) {
            float2 m = Vs[n*65 + o], v = vecs[g64][o];
            acc.x += m.x*v.x - m.y*v.y;
            acc.y += m.x*v.y + m.y*v.x;
        }
        // hr element pair (h*128+2n, +1) -> bf16x2 word h*64+n
        unsigned hw, lw;
        splitw(acc.x, acc.y, hw, lw);
        hrh[(size_t)l*HD + h*64 + n] = hw;
        hrl[(size_t)l*HD + h*64 + n] = lw;
        if (l == LL-1) {
            if (out_size >= OUT_Y + 2*HD) {
                out[OUT_Y + (h*64+n)*2]     = acc.x;
                out[OUT_Y + (h*64+n)*2 + 1] = acc.y;
            } else if (out_size >= OUT_Y + HD) {
                out[OUT_Y + h*64 + n] = acc.x;
            }
        }
        __syncthreads();
    }
}

// ---------------- launch ---------------------------------------------------
extern "C" void kernel_launch(void* const* d_in, const int* in_sizes, int n_in,
                              void* d_out, int out_size)
{
    const float* x        = (const float*)d_in[0];
    const float* hreal    = (const float*)d_in[1];
    const float* himag    = (const float*)d_in[2];
    const float* w_in1    = (const float*)d_in[3];
    const float* b_in1    = (const float*)d_in[4];
    const float* w_in2    = (const float*)d_in[5];
    const float* b_in2    = (const float*)d_in[6];
    const float* w_out1   = (const float*)d_in[7];
    const float* b_out1   = (const float*)d_in[8];
    const float* w_out2   = (const float*)d_in[9];
    const float* b_out2   = (const float*)d_in[10];
    const float* mvr      = (const float*)d_in[11];
    const float* mvi      = (const float*)d_in[12];
    float* out = (float*)d_out;

    float *part;
    float2 *xc, *a, *vinv, *w, *heig, *sP, *sQ, *sIn;
    cudaGetSymbolAddress((void**)&part, g_part);
    cudaGetSymbolAddress((void**)&xc,   g_xc);
    cudaGetSymbolAddress((void**)&a,    g_a);
    cudaGetSymbolAddress((void**)&vinv, g_vinv);
    cudaGetSymbolAddress((void**)&w,    g_w);
    cudaGetSymbolAddress((void**)&heig, g_heig);
    cudaGetSymbolAddress((void**)&sP,   g_sP);
    cudaGetSymbolAddress((void**)&sQ,   g_sQ);
    cudaGetSymbolAddress((void**)&sIn,  g_sIn);

    uint4 *xh,*xl,*w1h,*w1l,*w2h,*w2l,*o1h,*o1l,*o2h,*o2l,*t1h,*t1l,*hrh,*hrl,*y1h,*y1l;
    cudaGetSymbolAddress((void**)&xh,  g_xh);  cudaGetSymbolAddress((void**)&xl,  g_xl);
    cudaGetSymbolAddress((void**)&w1h, g_w1h); cudaGetSymbolAddress((void**)&w1l, g_w1l);
    cudaGetSymbolAddress((void**)&w2h, g_w2h); cudaGetSymbolAddress((void**)&w2l, g_w2l);
    cudaGetSymbolAddress((void**)&o1h, g_o1h); cudaGetSymbolAddress((void**)&o1l, g_o1l);
    cudaGetSymbolAddress((void**)&o2h, g_o2h); cudaGetSymbolAddress((void**)&o2l, g_o2l);
    cudaGetSymbolAddress((void**)&t1h, g_t1h); cudaGetSymbolAddress((void**)&t1l, g_t1l);
    cudaGetSymbolAddress((void**)&hrh, g_hrh); cudaGetSymbolAddress((void**)&hrl, g_hrl);
    cudaGetSymbolAddress((void**)&y1h, g_y1h); cudaGetSymbolAddress((void**)&y1l, g_y1l);

    cudaFuncSetAttribute(inv_kernel, cudaFuncAttributeMaxDynamicSharedMemorySize, 65536);

    const int MN1 = LL * DIMN;       // 262144

    // Vinv + operand pre-split (independent of each other)
    inv_kernel<<<HH, 1024, 65536>>>(mvr, mvi, vinv);
    conv_kernel<<<2688, 256>>>(x, w_in1, w_in2, w_out1, w_out2);

    // t1 = silu(x @ w_in1 + b_in1) -> bf16 hi/lo    split-K=4 (128 CTAs)
    gemm_bf<<<dim3(DIMN/128, LL/64, 4), 256>>>(
        (const ushort*)xh, (const ushort*)xl, (const ushort*)w1h, (const ushort*)w1l,
        part, LL, DIMN, DIMN, 4);
    reduce_bf<<<(MN1/4 + 255)/256, 256>>>(part, b_in1, t1h, t1l, MN1, DIMN, 4, 1);

    // t2 partials = t1 @ w_in2 ; fused reduce -> xc, a   split-K=2 (128 CTAs)
    gemm_bf<<<dim3(2*DIMN/128, LL/64, 2), 256>>>(
        (const ushort*)t1h, (const ushort*)t1l, (const ushort*)w2h, (const ushort*)w2l,
        part, LL, 2*DIMN, DIMN, 2);
    reduce_prep_kernel<<<(LL*HD + 255)/256, 256>>>(part, b_in2, xc, a, 2);

    // w[0..256] = Vinv @ [hidden, xc[0..255]]
    matvec_vinv_t<<<dim3(9, HH), 256>>>(vinv, xc, hreal, himag, w);

    // chunked diagonal recurrence
    scanA_kernel<<<16, HD>>>(a, w, sP, sQ);
    scanB_kernel<<<1, HD>>>(sP, sQ, sIn);
    scanC_kernel<<<16, HD>>>(a, w, sIn, heig);

    // back to original basis; emit bf16 hr + hidden_next
    matvec_v_t<<<dim3(8, HH), 256>>>(mvr, mvi, heig,
                                     (unsigned*)hrh, (unsigned*)hrl, out, out_size);

    // y1 = silu(hr @ w_out1 + b_out1) -> bf16 hi/lo   split-K=4
    gemm_bf<<<dim3(DIMN/128, LL/64, 4), 256>>>(
        (const ushort*)hrh, (const ushort*)hrl, (const ushort*)o1h, (const ushort*)o1l,
        part, LL, DIMN, DIMN, 4);
    reduce_bf<<<(MN1/4 + 255)/256, 256>>>(part, b_out1, y1h, y1l, MN1, DIMN, 4, 1);

    // y = y1 @ w_out2 + b_out2 -> d_out (f32)   split-K=4
    gemm_bf<<<dim3(DIMN/128, LL/64, 4), 256>>>(
        (const ushort*)y1h, (const ushort*)y1l, (const ushort*)o2h, (const ushort*)o2l,
        part, LL, DIMN, DIMN, 4);
    reduce_kernel<<<(MN1/4 + 255)/256, 256>>>(part, b_out2, out, MN1, DIMN, 4, 0);
}

// round 13
// speedup vs baseline: 1.0378x; 1.0062x over previous
#include <cuda_runtime.h>
#include <cuda_bf16.h>

// Shapes (fixed by the problem)
#define DIMN 1024
#define HH 8
#define DD 64
#define LL 256
#define HD 512           // H*D
#define OUT_Y (LL*DIMN)  // 262144

// ---------------- scratch (device globals; no allocation allowed) ----------
__device__ float  g_part[4*LL*DIMN];     // split-K partials (4MB max)
__device__ float2 g_xc[LL*HD];
__device__ float2 g_a[LL*HD];
__device__ float2 g_vinv[HH*DD*DD];
__device__ float2 g_w[(LL+1)*HD];
__device__ float2 g_heig[LL*HD];
__device__ float2 g_sP[16*HD];
__device__ float2 g_sQ[16*HD];
__device__ float2 g_sIn[16*HD];

// bf16 hi/lo pre-split operands (uint4 = 8 bf16)
__device__ uint4 g_xh [LL*DIMN/8],    g_xl [LL*DIMN/8];
__device__ uint4 g_w1h[DIMN*DIMN/8],  g_w1l[DIMN*DIMN/8];
__device__ uint4 g_w2h[DIMN*2*DIMN/8],g_w2l[DIMN*2*DIMN/8];
__device__ uint4 g_o1h[DIMN*DIMN/8],  g_o1l[DIMN*DIMN/8];
__device__ uint4 g_o2h[DIMN*DIMN/8],  g_o2l[DIMN*DIMN/8];
__device__ uint4 g_t1h[LL*DIMN/8],    g_t1l[LL*DIMN/8];
__device__ uint4 g_hrh[LL*DIMN/8],    g_hrl[LL*DIMN/8];
__device__ uint4 g_y1h[LL*DIMN/8],    g_y1l[LL*DIMN/8];

__device__ __forceinline__ float2 cmulf(float2 a, float2 b) {
    return make_float2(a.x*b.x - a.y*b.y, a.x*b.y + a.y*b.x);
}

// ---------------- bf16 split helpers ---------------------------------------
__device__ __forceinline__ unsigned pack2(float v0, float v1) {
    unsigned r;
    asm("cvt.rn.bf16x2.f32 %0, %1, %2;" : "=r"(r) : "f"(v1), "f"(v0));
    return r;
}
__device__ __forceinline__ void splitw(float v0, float v1, unsigned& h, unsigned& l) {
    h = pack2(v0, v1);
    float h0 = __uint_as_float(h << 16);
    float h1 = __uint_as_float(h & 0xFFFF0000u);
    l = pack2(v0 - h0, v1 - h1);
}
__device__ __forceinline__ void mma_bf16(float* c, const unsigned* a, const unsigned* b) {
    asm volatile(
        "mma.sync.aligned.m16n8k16.row.col.f32.bf16.bf16.f32 "
        "{%0,%1,%2,%3}, {%4,%5,%6,%7}, {%8,%9}, {%0,%1,%2,%3};\n"
        : "+f"(c[0]), "+f"(c[1]), "+f"(c[2]), "+f"(c[3])
        : "r"(a[0]), "r"(a[1]), "r"(a[2]), "r"(a[3]), "r"(b[0]), "r"(b[1]));
}
__device__ __forceinline__ void ldsm4(unsigned& r0, unsigned& r1, unsigned& r2, unsigned& r3, unsigned addr) {
    asm volatile("ldmatrix.sync.aligned.m8n8.x4.shared.b16 {%0,%1,%2,%3}, [%4];"
        : "=r"(r0), "=r"(r1), "=r"(r2), "=r"(r3) : "r"(addr));
}
__device__ __forceinline__ void ldsm4t(unsigned& r0, unsigned& r1, unsigned& r2, unsigned& r3, unsigned addr) {
    asm volatile("ldmatrix.sync.aligned.m8n8.x4.trans.shared.b16 {%0,%1,%2,%3}, [%4];"
        : "=r"(r0), "=r"(r1), "=r"(r2), "=r"(r3) : "r"(addr));
}
__device__ __forceinline__ void cpasync16(unsigned saddr, const void* gaddr) {
    asm volatile("cp.async.cg.shared.global [%0], [%1], 16;" :: "r"(saddr), "l"(gaddr));
}

// ---------------- conv: f32 tensors -> bf16 hi/lo arrays -------------------
__device__ __forceinline__ void conv8(const float* __restrict__ s,
                                      uint4* __restrict__ dh, uint4* __restrict__ dl,
                                      int i)
{
    float4 v0 = ((const float4*)s)[2*i];
    float4 v1 = ((const float4*)s)[2*i+1];
    uint4 h, l;
    splitw(v0.x, v0.y, h.x, l.x); splitw(v0.z, v0.w, h.y, l.y);
    splitw(v1.x, v1.y, h.z, l.z); splitw(v1.z, v1.w, h.w, l.w);
    dh[i] = h; dl[i] = l;
}
// tasks: x 32768 | w_in1 131072 | w_in2 262144 | w_out1 131072 | w_out2 131072
__global__ void conv_kernel(const float* __restrict__ x,
                            const float* __restrict__ w1,
                            const float* __restrict__ w2,
                            const float* __restrict__ o1,
                            const float* __restrict__ o2)
{
    int id = blockIdx.x*blockDim.x + threadIdx.x;
    if      (id < 32768)  conv8(x,  g_xh,  g_xl,  id);
    else if (id < 163840) conv8(w1, g_w1h, g_w1l, id - 32768);
    else if (id < 425984) conv8(w2, g_w2h, g_w2l, id - 163840);
    else if (id < 557056) conv8(o1, g_o1h, g_o1l, id - 425984);
    else                  conv8(o2, g_o2h, g_o2l, id - 557056);
}

// ---------------- split-K bf16 GEMM: P[z] = Ah@Bh + Ah@Bl + Al@Bh ----------
// Block 64x128, BK=32, 8 warps (2M x 4N), warp 32x32, m16n8k16.
// 3-stage cp.async pipeline, one __syncthreads per chunk.
// per-stage element offsets (ushort): Ah 0, Al 2560, Bh 5120, Bl 9472 (13824)
#define SA_PITCH 40    // A row pitch (32 + 8) elements
#define SB_PITCH 136   // B row pitch (128 + 8) elements
#define OFF_AL 2560
#define OFF_BH 5120
#define OFF_BL 9472
#define STAGE_BYTES 27648   // 13824 ushorts
__global__ __launch_bounds__(256) void gemm_bf(
    const ushort* __restrict__ Ah, const ushort* __restrict__ Al,
    const ushort* __restrict__ Bh, const ushort* __restrict__ Bl,
    float* __restrict__ P, int M, int N, int K, int ksplit)
{
    extern __shared__ ushort sm[];

    const int tid  = threadIdx.x;
    const int lane = tid & 31;
    const int wid  = tid >> 5;
    const int wm   = wid & 1;
    const int wn   = wid >> 1;

    const int ksub = K / ksplit;
    const int k0g  = blockIdx.z * ksub;
    const int nc   = ksub >> 5;

    float acc[2][4][4] = {};

    // copy assignments
    const int arow = tid >> 2;             // 0..63
    const int ak8  = (tid & 3) << 3;       // 0,8,16,24
    const ushort* Aph = Ah + (size_t)(blockIdx.y*64 + arow)*K + k0g + ak8;
    const ushort* Apl = Al + (size_t)(blockIdx.y*64 + arow)*K + k0g + ak8;
    // B: two segments per matrix
    const int bi0 = tid,        bk0 = bi0 >> 4, bn0 = (bi0 & 15) << 3;
    const int bi1 = tid + 256,  bk1 = bi1 >> 4, bn1 = (bi1 & 15) << 3;
    const ushort* Bph = Bh + (size_t)k0g*N + blockIdx.x*128;
    const ushort* Bpl = Bl + (size_t)k0g*N + blockIdx.x*128;

    const unsigned smem_u = (unsigned)__cvta_generic_to_shared(sm);
    // per-thread store byte-offsets within a stage
    const unsigned sa_h  = 2*(arow*SA_PITCH + ak8);
    const unsigned sa_l  = sa_h + 2*OFF_AL;
    const unsigned sb_h0 = 2*(OFF_BH + bk0*SB_PITCH + bn0);
    const unsigned sb_h1 = 2*(OFF_BH + bk1*SB_PITCH + bn1);
    const unsigned sb_l0 = sb_h0 + 2*(OFF_BL - OFF_BH);
    const unsigned sb_l1 = sb_h1 + 2*(OFF_BL - OFF_BH);
    // ldmatrix lane offsets
    const int aoff = ((lane & 7) + ((lane >> 3) & 1)*8)*SA_PITCH + ((lane >> 4) & 1)*8;
    const int boff = ((lane >> 4)*16 + ((lane >> 3) & 1)*8 + (lane & 7))*SB_PITCH;

    // pipeline: issue chunk c into stage c%3
    auto issue = [&](int c) {
        unsigned base = smem_u + (unsigned)(c % 3) * STAGE_BYTES;
        int kd = c * 32;
        cpasync16(base + sa_h,  Aph + kd);
        cpasync16(base + sa_l,  Apl + kd);
        cpasync16(base + sb_h0, Bph + (size_t)(kd + bk0)*N + bn0);
        cpasync16(base + sb_h1, Bph + (size_t)(kd + bk1)*N + bn1);
        cpasync16(base + sb_l0, Bpl + (size_t)(kd + bk0)*N + bn0);
        cpasync16(base + sb_l1, Bpl + (size_t)(kd + bk1)*N + bn1);
        asm volatile("cp.async.commit_group;");
    };

    issue(0);
    if (nc > 1) issue(1);

    for (int c = 0; c < nc; c++) {
        if (c + 1 < nc) { asm volatile("cp.async.wait_group 1;"); }
        else            { asm volatile("cp.async.wait_group 0;"); }
        __syncthreads();
        if (c + 2 < nc) issue(c + 2);

        const unsigned sbase = smem_u + (unsigned)(c % 3) * STAGE_BYTES;

        // A fragments: 8 ldmatrix.x4 (hi + lo for 2ma x 2ka)
        unsigned ah[2][2][4], al_[2][2][4];
#pragma unroll
        for (int ma = 0; ma < 2; ma++)
#pragma unroll
            for (int ka = 0; ka < 2; ka++) {
                unsigned base = sbase + 2*((wm*32 + ma*16)*SA_PITCH + ka*16 + aoff);
                ldsm4(ah[ma][ka][0], ah[ma][ka][1], ah[ma][ka][2], ah[ma][ka][3], base);
                ldsm4(al_[ma][ka][0], al_[ma][ka][1], al_[ma][ka][2], al_[ma][ka][3],
                      base + 2*OFF_AL);
            }

        // per-na: B fragments (2 ldmatrix.x4.trans) + 12 MMA
#pragma unroll
        for (int na = 0; na < 4; na++) {
            unsigned bh4[4], bl4[4];
            unsigned baseb = sbase + 2*(OFF_BH + boff + wn*32 + na*8);
            ldsm4t(bh4[0], bh4[1], bh4[2], bh4[3], baseb);
            ldsm4t(bl4[0], bl4[1], bl4[2], bl4[3], baseb + 2*(OFF_BL - OFF_BH));
#pragma unroll
            for (int ma = 0; ma < 2; ma++)
#pragma unroll
                for (int ka = 0; ka < 2; ka++) {
                    mma_bf16(acc[ma][na], al_[ma][ka], &bh4[ka*2]);
                    mma_bf16(acc[ma][na], ah[ma][ka],  &bl4[ka*2]);
                    mma_bf16(acc[ma][na], ah[ma][ka],  &bh4[ka*2]);
                }
        }
    }

    const int g   = lane >> 2;
    const int tig = lane & 3;
    float* Pz = P + (size_t)blockIdx.z * M * N;
#pragma unroll
    for (int ma = 0; ma < 2; ma++) {
#pragma unroll
        for (int na = 0; na < 4; na++) {
            int row = blockIdx.y*64 + wm*32 + ma*16 + g;
            int col = blockIdx.x*128 + wn*32 + na*8 + 2*tig;
            *(float2*)&Pz[(size_t)row*N + col]     = make_float2(acc[ma][na][0], acc[ma][na][1]);
            *(float2*)&Pz[(size_t)(row+8)*N + col] = make_float2(acc[ma][na][2], acc[ma][na][3]);
        }
    }
}

// ---------------- reduce split-K partials + bias + silu -> bf16 hi/lo ------
__global__ void reduce_bf(const float* __restrict__ P,
                          const float* __restrict__ bias,
                          uint4* __restrict__ outh, uint4* __restrict__ outl,
                          int MN, int N, int ksplit, int act)
{
    int gid = blockIdx.x*blockDim.x + threadIdx.x;
    int e = gid * 4;
    if (e >= MN) return;
    float4 s = *(const float4*)(P + e);
    for (int z = 1; z < ksplit; z++) {
        float4 p = *(const float4*)(P + (size_t)z*MN + e);
        s.x += p.x; s.y += p.y; s.z += p.z; s.w += p.w;
    }
    int c = e % N;
    float4 b = *(const float4*)(bias + c);
    s.x += b.x; s.y += b.y; s.z += b.z; s.w += b.w;
    if (act) {
        s.x = s.x / (1.0f + expf(-s.x));
        s.y = s.y / (1.0f + expf(-s.y));
        s.z = s.z / (1.0f + expf(-s.z));
        s.w = s.w / (1.0f + expf(-s.w));
    }
    uint2 h, l;
    splitw(s.x, s.y, h.x, l.x);
    splitw(s.z, s.w, h.y, l.y);
    ((uint2*)outh)[gid] = h;
    ((uint2*)outl)[gid] = l;
}

// ---------------- reduce split-K partials + bias -> f32 (final y) ----------
__global__ void reduce_kernel(const float* __restrict__ P,
                              const float* __restrict__ bias,
                              float* __restrict__ C,
                              int MN, int N, int ksplit, int act)
{
    int e = (blockIdx.x*blockDim.x + threadIdx.x) * 4;
    if (e >= MN) return;
    float4 s = *(const float4*)(P + e);
    for (int z = 1; z < ksplit; z++) {
        float4 p = *(const float4*)(P + (size_t)z*MN + e);
        s.x += p.x; s.y += p.y; s.z += p.z; s.w += p.w;
    }
    int c = e % N;
    float4 b = *(const float4*)(bias + c);
    s.x += b.x; s.y += b.y; s.z += b.z; s.w += b.w;
    if (act) {
        s.x = s.x / (1.0f + expf(-s.x));
        s.y = s.y / (1.0f + expf(-s.y));
        s.z = s.z / (1.0f + expf(-s.z));
        s.w = s.w / (1.0f + expf(-s.w));
    }
    *(float4*)(C + e) = s;
}

// ---------------- reduce partials of GEMM2 and emit xc + normalized a ------
__global__ void reduce_prep_kernel(const float* __restrict__ P,
                                   const float* __restrict__ bias,
                                   float2* __restrict__ xc, float2* __restrict__ a,
                                   int ksplit)
{
    int e = blockIdx.x*blockDim.x + threadIdx.x;   // 0 .. LL*HD-1
    if (e >= LL*HD) return;
    const int MN = LL * 2 * DIMN;
    int off = e * 4;
    float4 s = *(const float4*)(P + off);
    for (int z = 1; z < ksplit; z++) {
        float4 p = *(const float4*)(P + (size_t)z*MN + off);
        s.x += p.x; s.y += p.y; s.z += p.z; s.w += p.w;
    }
    int c = off % (2*DIMN);
    float4 b = *(const float4*)(bias + c);
    float xr = s.x + b.x, xi = s.y + b.y, ar = s.z + b.z, ai = s.w + b.w;
    xc[e] = make_float2(xr, xi);
    float m2 = ar*ar + ai*ai;
    float f = (m2/(1.0f+m2)) * rsqrtf(m2);   // sigmoid(log m2) * rsqrt(m2)
    a[e] = make_float2(ar*f, ai*f);
}

// ---------------- complex 64x64 inverse (Gauss-Jordan, partial pivot) ------
__global__ __launch_bounds__(1024) void inv_kernel(
    const float* __restrict__ vr, const float* __restrict__ vi,
    float2* __restrict__ vinv)
{
    extern __shared__ float2 sh[];
    float2* Am = sh;          // 64*64
    float2* Im = sh + 4096;   // 64*64
    __shared__ float2 fac[64];
    __shared__ float2 pivval;
    __shared__ int piv;
    int h = blockIdx.x;
    int t = threadIdx.x;   // 1024 threads

    for (int i = t; i < 4096; i += 1024) {
        int n = i >> 6, o = i & 63;
        Am[i] = make_float2(vr[h*4096 + i], vi[h*4096 + i]);
        Im[i] = make_float2(n == o ? 1.0f : 0.0f, 0.0f);
    }
    __syncthreads();

    for (int k = 0; k < 64; k++) {
        if (t < 32) {
            float best = -1.0f; int bp = k;
            for (int r = k + t; r < 64; r += 32) {
                float2 v = Am[r*64+k];
                float m = v.x*v.x + v.y*v.y;
                if (m > best) { best = m; bp = r; }
            }
#pragma unroll
            for (int o = 16; o; o >>= 1) {
                float ob = __shfl_down_sync(0xffffffffu, best, o);
                int  obp = __shfl_down_sync(0xffffffffu, bp,   o);
                if (ob > best) { best = ob; bp = obp; }
            }
            if (t == 0) { piv = bp; pivval = Am[bp*64+k]; }
        }
        __syncthreads();
        const int p = piv;
        const float2 pv = pivval;
        const float im2 = 1.0f/(pv.x*pv.x + pv.y*pv.y);
        const float2 pinv = make_float2(pv.x*im2, -pv.y*im2);

        if (t < 128) {
            float2* Mm = (t < 64) ? Am : Im;
            int c = t & 63;
            float2 rp = Mm[p*64+c];
            float2 rk = Mm[k*64+c];
            Mm[k*64+c] = cmulf(rp, pinv);
            if (p != k) Mm[p*64+c] = rk;
        }
        __syncthreads();
        if (t < 64) fac[t] = Am[t*64+k];
        __syncthreads();

        {
            int c = t & 63;
            float2* Mm = ((t >> 6) & 1) ? Im : Am;
            int rs = t >> 7;                 // 0..7
            float2 pk = Mm[k*64+c];
#pragma unroll 8
            for (int r = rs; r < 64; r += 8) {
                if (r == k) continue;
                float2 f = fac[r];
                float2 v = Mm[r*64+c];
                v.x -= f.x*pk.x - f.y*pk.y;
                v.y -= f.x*pk.y + f.y*pk.x;
                Mm[r*64+c] = v;
            }
        }
        __syncthreads();
    }
    for (int i = t; i < 4096; i += 1024) vinv[h*4096 + i] = Im[i];
}

// ---------------- tiled matvec: w[li] = Vinv[h] @ [hidden | xc[li-1]] ------
__global__ __launch_bounds__(256) void matvec_vinv_t(
    const float2* __restrict__ vinv, const float2* __restrict__ xc,
    const float* __restrict__ hreal, const float* __restrict__ himag,
    float2* __restrict__ w)
{
    __shared__ float2 Vs[64*65];
    __shared__ float2 vecs[4][64];
    const int lc = blockIdx.x;   // 0..8
    const int h  = blockIdx.y;
    const int tid = threadIdx.x;
    for (int i = tid; i < 4096; i += 256) {
        int n = i >> 6, o = i & 63;
        Vs[n*65 + o] = vinv[h*4096 + i];
    }
    __syncthreads();
    const int g64 = tid >> 6;    // 0..3
    const int n   = tid & 63;
    for (int rep = 0; rep < 8; rep++) {
        int li = lc*32 + rep*4 + g64;
        if (li <= LL) {
            if (li == 0) vecs[g64][n] = make_float2(hreal[h*64+n], himag[h*64+n]);
            else         vecs[g64][n] = xc[(li-1)*HD + h*64 + n];
        }
        __syncthreads();
        if (li <= LL) {
            float2 acc = make_float2(0.0f, 0.0f);
#pragma unroll 8
            for (int o = 0; o < 64; o++) {
                float2 m = Vs[n*65 + o], v = vecs[g64][o];
                acc.x += m.x*v.x - m.y*v.y;
                acc.y += m.x*v.y + m.y*v.x;
            }
            w[li*HD + h*64 + n] = acc;
        }
        __syncthreads();
    }
}

// ---------------- chunked scan: s[m] = a[m]*(s[m-1]+w[m]) ------------------
__global__ void scanA_kernel(const float2* __restrict__ a,
                             const float2* __restrict__ w,
                             float2* __restrict__ sP, float2* __restrict__ sQ)
{
    int c = blockIdx.x;      // 0..15
    int hd = threadIdx.x;    // 0..511
    float2 Pp = make_float2(1.0f, 0.0f);
    float2 S  = make_float2(0.0f, 0.0f);
#pragma unroll
    for (int i = 0; i < 16; i++) {
        int m = c*16 + i;
        float2 wm = w[m*HD + hd];
        float2 am = a[m*HD + hd];
        float2 t = make_float2(S.x + wm.x, S.y + wm.y);
        S  = cmulf(am, t);
        Pp = cmulf(am, Pp);
    }
    sP[c*HD + hd] = Pp;
    sQ[c*HD + hd] = S;
}
__global__ void scanB_kernel(const float2* __restrict__ sP,
                             const float2* __restrict__ sQ,
                             float2* __restrict__ sIn)
{
    int hd = threadIdx.x;
    float2 s = make_float2(0.0f, 0.0f);
#pragma unroll
    for (int c = 0; c < 16; c++) {
        sIn[c*HD + hd] = s;
        float2 p = sP[c*HD + hd];
        float2 q = sQ[c*HD + hd];
        float2 t = cmulf(p, s);
        s = make_float2(t.x + q.x, t.y + q.y);
    }
}
__global__ void scanC_kernel(const float2* __restrict__ a,
                             const float2* __restrict__ w,
                             const float2* __restrict__ sIn,
                             float2* __restrict__ heig)
{
    int c = blockIdx.x;
    int hd = threadIdx.x;
    float2 s = sIn[c*HD + hd];
#pragma unroll
    for (int i = 0; i < 16; i++) {
        int m = c*16 + i;
        float2 wm = w[m*HD + hd];
        float2 am = a[m*HD + hd];
        float2 t = make_float2(s.x + wm.x, s.y + wm.y);
        s = cmulf(am, t);
        float2 wn = w[(m+1)*HD + hd];
        heig[m*HD + hd] = make_float2(s.x + wn.x, s.y + wn.y);
    }
}

// ---------------- tiled matvec: out_h[l] = V[h] @ heig[l]; emit bf16 hr ----
__global__ __launch_bounds__(256) void matvec_v_t(
    const float* __restrict__ vr, const float* __restrict__ vi,
    const float2* __restrict__ heig,
    unsigned* __restrict__ hrh, unsigned* __restrict__ hrl,
    float* __restrict__ out, int out_size)
{
    __shared__ float2 Vs[64*65];
    __shared__ float2 vecs[4][64];
    const int lc = blockIdx.x;   // 0..7
    const int h  = blockIdx.y;
    const int tid = threadIdx.x;
    for (int i = tid; i < 4096; i += 256) {
        int n = i >> 6, o = i & 63;
        Vs[n*65 + o] = make_float2(vr[h*4096 + i], vi[h*4096 + i]);
    }
    __syncthreads();
    const int g64 = tid >> 6;
    const int n   = tid & 63;
    for (int rep = 0; rep < 8; rep++) {
        int l = lc*32 + rep*4 + g64;
        vecs[g64][n] = heig[l*HD + h*64 + n];
        __syncthreads();
        float2 acc = make_float2(0.0f, 0.0f);
#pragma unroll 8
        for (int o = 0; o < 64; o++) {
            float2 m = Vs[n*65 + o], v = vecs[g64][o];
            acc.x += m.x*v.x - m.y*v.y;
            acc.y += m.x*v.y + m.y*v.x;
        }
        // hr element pair (h*128+2n, +1) -> bf16x2 word h*64+n
        unsigned hw, lw;
        splitw(acc.x, acc.y, hw, lw);
        hrh[(size_t)l*HD + h*64 + n] = hw;
        hrl[(size_t)l*HD + h*64 + n] = lw;
        if (l == LL-1) {
            if (out_size >= OUT_Y + 2*HD) {
                out[OUT_Y + (h*64+n)*2]     = acc.x;
                out[OUT_Y + (h*64+n)*2 + 1] = acc.y;
            } else if (out_size >= OUT_Y + HD) {
                out[OUT_Y + h*64 + n] = acc.x;
            }
        }
        __syncthreads();
    }
}

// ---------------- launch ---------------------------------------------------
extern "C" void kernel_launch(void* const* d_in, const int* in_sizes, int n_in,
                              void* d_out, int out_size)
{
    const float* x        = (const float*)d_in[0];
    const float* hreal    = (const float*)d_in[1];
    const float* himag    = (const float*)d_in[2];
    const float* w_in1    = (const float*)d_in[3];
    const float* b_in1    = (const float*)d_in[4];
    const float* w_in2    = (const float*)d_in[5];
    const float* b_in2    = (const float*)d_in[6];
    const float* w_out1   = (const float*)d_in[7];
    const float* b_out1   = (const float*)d_in[8];
    const float* w_out2   = (const float*)d_in[9];
    const float* b_out2   = (const float*)d_in[10];
    const float* mvr      = (const float*)d_in[11];
    const float* mvi      = (const float*)d_in[12];
    float* out = (float*)d_out;

    float *part;
    float2 *xc, *a, *vinv, *w, *heig, *sP, *sQ, *sIn;
    cudaGetSymbolAddress((void**)&part, g_part);
    cudaGetSymbolAddress((void**)&xc,   g_xc);
    cudaGetSymbolAddress((void**)&a,    g_a);
    cudaGetSymbolAddress((void**)&vinv, g_vinv);
    cudaGetSymbolAddress((void**)&w,    g_w);
    cudaGetSymbolAddress((void**)&heig, g_heig);
    cudaGetSymbolAddress((void**)&sP,   g_sP);
    cudaGetSymbolAddress((void**)&sQ,   g_sQ);
    cudaGetSymbolAddress((void**)&sIn,  g_sIn);

    uint4 *xh,*xl,*w1h,*w1l,*w2h,*w2l,*o1h,*o1l,*o2h,*o2l,*t1h,*t1l,*hrh,*hrl,*y1h,*y1l;
    cudaGetSymbolAddress((void**)&xh,  g_xh);  cudaGetSymbolAddress((void**)&xl,  g_xl);
    cudaGetSymbolAddress((void**)&w1h, g_w1h); cudaGetSymbolAddress((void**)&w1l, g_w1l);
    cudaGetSymbolAddress((void**)&w2h, g_w2h); cudaGetSymbolAddress((void**)&w2l, g_w2l);
    cudaGetSymbolAddress((void**)&o1h, g_o1h); cudaGetSymbolAddress((void**)&o1l, g_o1l);
    cudaGetSymbolAddress((void**)&o2h, g_o2h); cudaGetSymbolAddress((void**)&o2l, g_o2l);
    cudaGetSymbolAddress((void**)&t1h, g_t1h); cudaGetSymbolAddress((void**)&t1l, g_t1l);
    cudaGetSymbolAddress((void**)&hrh, g_hrh); cudaGetSymbolAddress((void**)&hrl, g_hrl);
    cudaGetSymbolAddress((void**)&y1h, g_y1h); cudaGetSymbolAddress((void**)&y1l, g_y1l);

    cudaFuncSetAttribute(inv_kernel, cudaFuncAttributeMaxDynamicSharedMemorySize, 65536);
    cudaFuncSetAttribute(gemm_bf, cudaFuncAttributeMaxDynamicSharedMemorySize, 3*STAGE_BYTES);

    const int MN1 = LL * DIMN;       // 262144
    const int GSM = 3*STAGE_BYTES;   // 82944

    // Vinv + operand pre-split (independent of each other)
    inv_kernel<<<HH, 1024, 65536>>>(mvr, mvi, vinv);
    conv_kernel<<<2688, 256>>>(x, w_in1, w_in2, w_out1, w_out2);

    // t1 = silu(x @ w_in1 + b_in1) -> bf16 hi/lo    split-K=4 (128 CTAs)
    gemm_bf<<<dim3(DIMN/128, LL/64, 4), 256, GSM>>>(
        (const ushort*)xh, (const ushort*)xl, (const ushort*)w1h, (const ushort*)w1l,
        part, LL, DIMN, DIMN, 4);
    reduce_bf<<<(MN1/4 + 255)/256, 256>>>(part, b_in1, t1h, t1l, MN1, DIMN, 4, 1);

    // t2 partials = t1 @ w_in2 ; fused reduce -> xc, a   split-K=2 (128 CTAs)
    gemm_bf<<<dim3(2*DIMN/128, LL/64, 2), 256, GSM>>>(
        (const ushort*)t1h, (const ushort*)t1l, (const ushort*)w2h, (const ushort*)w2l,
        part, LL, 2*DIMN, DIMN, 2);
    reduce_prep_kernel<<<(LL*HD + 255)/256, 256>>>(part, b_in2, xc, a, 2);

    // w[0..256] = Vinv @ [hidden, xc[0..255]]
    matvec_vinv_t<<<dim3(9, HH), 256>>>(vinv, xc, hreal, himag, w);

    // chunked diagonal recurrence
    scanA_kernel<<<16, HD>>>(a, w, sP, sQ);
    scanB_kernel<<<1, HD>>>(sP, sQ, sIn);
    scanC_kernel<<<16, HD>>>(a, w, sIn, heig);

    // back to original basis; emit bf16 hr + hidden_next
    matvec_v_t<<<dim3(8, HH), 256>>>(mvr, mvi, heig,
                                     (unsigned*)hrh, (unsigned*)hrl, out, out_size);

    // y1 = silu(hr @ w_out1 + b_out1) -> bf16 hi/lo   split-K=4
    gemm_bf<<<dim3(DIMN/128, LL/64, 4), 256, GSM>>>(
        (const ushort*)hrh, (const ushort*)hrl, (const ushort*)o1h, (const ushort*)o1l,
        part, LL, DIMN, DIMN, 4);
    reduce_bf<<<(MN1/4 + 255)/256, 256>>>(part, b_out1, y1h, y1l, MN1, DIMN, 4, 1);

    // y = y1 @ w_out2 + b_out2 -> d_out (f32)   split-K=4
    gemm_bf<<<dim3(DIMN/128, LL/64, 4), 256, GSM>>>(
        (const ushort*)y1h, (const ushort*)y1l, (const ushort*)o2h, (const ushort*)o2l,
        part, LL, DIMN, DIMN, 4);
    reduce_kernel<<<(MN1/4 + 255)/256, 256>>>(part, b_out2, out, MN1, DIMN, 4, 0);
}